// round 11
// baseline (speedup 1.0000x reference)
#include <cuda_runtime.h>
#include <cstdint>
#include <cstddef>

#define TN      16
#define MP      8
#define DD      256
#define HH      256
#define NTOT    100000
#define THREADS 256

// float-unit strides / offsets in dynamic SMEM
#define A_STRIDE 260           // A [128][260]  pad: bank (4r+k)%32 conflict-free
#define B_STRIDE 20            // B chunk [256][20] bank (20n+k)%32 conflict-free
#define T_STRIDE 18            // tgt [256][18]

#define F_A     0
#define F_B     (128 * A_STRIDE)                 // 33280
#define F_TGT   (F_B + 3 * 256 * B_STRIDE)       // 48640
#define F_BIAS  (F_TGT + 256 * T_STRIDE)         // 53248
#define F_TNSQ  (F_BIAS + 256)                   // 53504  [16 seg][16 j]
#define F_TNRM  (F_TNSQ + 256)                   // 53760  [16]
#define F_REDD  (F_TNRM + 16)                    // 53776  [2 wn][8 m][16 j]
#define F_REDN  (F_REDD + 256)                   // 54032
#define F_COS   (F_REDN + 256)                   // 54288  [128]
#define F_ATT   (F_COS + 128)                    // 54416  [128]
#define F_END   (F_ATT + 128)                    // 54544 floats
#define SMEM_REQ (F_END * 4)                     // 218176 bytes

// ---------------- PTX helpers ----------------
__device__ __forceinline__ uint32_t smem_u32(const void* p) {
    uint32_t a;
    asm("{ .reg .u64 t; cvta.to.shared.u64 t, %1; cvt.u32.u64 %0, t; }" : "=r"(a) : "l"(p));
    return a;
}
__device__ __forceinline__ void cp16(uint32_t dst, const void* src) {
    asm volatile("cp.async.cg.shared.global [%0], [%1], 16;" :: "r"(dst), "l"(src));
}
__device__ __forceinline__ void cp_commit() {
    asm volatile("cp.async.commit_group;" ::: "memory");
}
template <int N>
__device__ __forceinline__ void cp_wait() {
    asm volatile("cp.async.wait_group %0;" :: "n"(N) : "memory");
}
__device__ __forceinline__ void mma_tf32(float& d0, float& d1, float& d2, float& d3,
                                         uint32_t a0, uint32_t a1, uint32_t a2, uint32_t a3,
                                         uint32_t b0, uint32_t b1) {
    asm volatile(
        "mma.sync.aligned.m16n8k8.row.col.f32.tf32.tf32.f32 "
        "{%0,%1,%2,%3}, {%4,%5,%6,%7}, {%8,%9}, {%0,%1,%2,%3};"
        : "+f"(d0), "+f"(d1), "+f"(d2), "+f"(d3)
        : "r"(a0), "r"(a1), "r"(a2), "r"(a3), "r"(b0), "r"(b1));
}
__device__ __forceinline__ float tanh_fast(float x) {
    float r; asm("tanh.approx.f32 %0, %1;" : "=f"(r) : "f"(x)); return r;
}

// ---------------- kernel ----------------
__global__ void __launch_bounds__(THREADS, 1)
hete_attn_kernel(const int* __restrict__ nodes,
                 const float* __restrict__ homo,
                 const float* __restrict__ Wg,
                 const float* __restrict__ bg,
                 const float* __restrict__ outemb,
                 float* __restrict__ outp)
{
    extern __shared__ float s[];
    const uint32_t sb = smem_u32(s);
    const int tid  = threadIdx.x;
    const int wid  = tid >> 5;
    const int lane = tid & 31;
    const int wm   = wid & 3;       // M-tile 0..3 (rows wm*32..+32)
    const int wn   = wid >> 2;      // N-tile 0..1 (cols wn*128..+128)
    const int n0   = blockIdx.x * TN;

    const uint32_t* Au = (const uint32_t*)(s + F_A);
    const float*    tg = s + F_TGT;

    // ---- prologue: async stage A (raw fp32) + first 3 B chunks ----
    #pragma unroll
    for (int i = 0; i < 32; i++) {                  // A: 128 rows x 1KB
        int idx = i * THREADS + tid;
        int r = idx >> 6, f4 = idx & 63;
        int m = r >> 4, j = r & 15;
        cp16(sb + (uint32_t)(F_A + r * A_STRIDE + f4 * 4) * 4,
             homo + ((size_t)m * NTOT + n0 + j) * DD + f4 * 4);
    }
    #pragma unroll
    for (int sB = 0; sB < 4; sB++) {                // B chunk 0
        int idx = sB * THREADS + tid;
        int n = idx >> 2, q = idx & 3;
        cp16(sb + (uint32_t)(F_B + n * B_STRIDE + q * 4) * 4,
             Wg + (size_t)n * DD + q * 4);
    }
    cp_commit();                                     // group0: A + B0
    #pragma unroll
    for (int c = 1; c < 3; c++) {                    // B chunks 1,2
        #pragma unroll
        for (int sB = 0; sB < 4; sB++) {
            int idx = sB * THREADS + tid;
            int n = idx >> 2, q = idx & 3;
            cp16(sb + (uint32_t)(F_B + c * 256 * B_STRIDE + n * B_STRIDE + q * 4) * 4,
                 Wg + (size_t)n * DD + c * 16 + q * 4);
        }
        cp_commit();                                 // group1, group2
    }

    s[F_BIAS + tid] = bg[tid];
    // tgt gather -> transposed [h][j], stride 18
    #pragma unroll
    for (int sT = 0; sT < 4; sT++) {
        int idx = sT * THREADS + tid;
        int j = idx >> 6, f4 = idx & 63;
        int nd = nodes[n0 + j];
        float4 v = __ldg((const float4*)(outemb + (size_t)nd * HH) + f4);
        float* dst = s + F_TGT;
        dst[(4 * f4 + 0) * T_STRIDE + j] = v.x;
        dst[(4 * f4 + 1) * T_STRIDE + j] = v.y;
        dst[(4 * f4 + 2) * T_STRIDE + j] = v.z;
        dst[(4 * f4 + 3) * T_STRIDE + j] = v.w;
    }

    cp_wait<2>();          // A + B0 complete
    __syncthreads();

    // partial ||tgt||^2
    {
        int j = tid & 15, seg = tid >> 4;
        float a0 = 0.f;
        #pragma unroll
        for (int e = 0; e < 16; e++) {
            float v = tg[(seg * 16 + e) * T_STRIDE + j];
            a0 += v * v;
        }
        s[F_TNSQ + seg * 16 + j] = a0;
    }

    // ---- mainloop: 16 K-chunks of 16, triple-buffered B ----
    float acc[2][16][4];
    #pragma unroll
    for (int ms = 0; ms < 2; ms++)
        #pragma unroll
        for (int nt = 0; nt < 16; nt++)
            #pragma unroll
            for (int e = 0; e < 4; e++) acc[ms][nt][e] = 0.f;

    const int g  = lane >> 2;       // 0..7
    const int l3 = lane & 3;        // 0..3

    for (int c = 0; c < 16; ++c) {
        const uint32_t* Bu = (const uint32_t*)(s + F_B + (c % 3) * 256 * B_STRIDE);
        #pragma unroll
        for (int ks = 0; ks < 2; ks++) {
            const int kg = c * 16 + ks * 8 + l3;    // global k for A
            const int kl = ks * 8 + l3;             // local k for B
            uint32_t a0[2], a1[2], a2[2], a3[2];
            #pragma unroll
            for (int ms = 0; ms < 2; ms++) {
                int r = wm * 32 + ms * 16 + g;
                a0[ms] = Au[r * A_STRIDE + kg];
                a1[ms] = Au[(r + 8) * A_STRIDE + kg];
                a2[ms] = Au[r * A_STRIDE + kg + 4];
                a3[ms] = Au[(r + 8) * A_STRIDE + kg + 4];
            }
            #pragma unroll
            for (int nt = 0; nt < 16; nt++) {
                int n = wn * 128 + nt * 8 + g;
                uint32_t b0 = Bu[n * B_STRIDE + kl];
                uint32_t b1 = Bu[n * B_STRIDE + kl + 4];
                #pragma unroll
                for (int ms = 0; ms < 2; ms++)
                    mma_tf32(acc[ms][nt][0], acc[ms][nt][1], acc[ms][nt][2], acc[ms][nt][3],
                             a0[ms], a1[ms], a2[ms], a3[ms], b0, b1);
            }
        }
        __syncthreads();                             // all warps done with buf c%3
        if (c == 0 && tid < 16) {                    // finalize ||tgt||
            float sum = 0.f;
            #pragma unroll
            for (int e = 0; e < 16; e++) sum += s[F_TNSQ + e * 16 + tid];
            s[F_TNRM + tid] = fmaxf(sqrtf(sum), 1e-8f);
        }
        if (c + 3 < 16) {                            // stage chunk c+3
            int cc = c + 3, buf = cc % 3;
            #pragma unroll
            for (int sB = 0; sB < 4; sB++) {
                int idx = sB * THREADS + tid;
                int n = idx >> 2, q = idx & 3;
                cp16(sb + (uint32_t)(F_B + buf * 256 * B_STRIDE + n * B_STRIDE + q * 4) * 4,
                     Wg + (size_t)n * DD + cc * 16 + q * 4);
            }
            cp_commit();
        }
        if (c < 15) {
            if (c <= 12)      cp_wait<2>();
            else if (c == 13) cp_wait<1>();
            else              cp_wait<0>();
            __syncthreads();
        }
    }

    // ---- epilogue: tanh + dot/norm (register accumulators) ----
    {
        float dot[2][2] = {{0.f, 0.f}, {0.f, 0.f}};
        float nrm[2][2] = {{0.f, 0.f}, {0.f, 0.f}};
        #pragma unroll
        for (int nt = 0; nt < 16; nt++) {
            int nc = wn * 128 + nt * 8 + 2 * l3;
            float bias0 = s[F_BIAS + nc];
            float bias1 = s[F_BIAS + nc + 1];
            float t0a = tg[nc * T_STRIDE + g];
            float t1a = tg[(nc + 1) * T_STRIDE + g];
            float t0b = tg[nc * T_STRIDE + g + 8];
            float t1b = tg[(nc + 1) * T_STRIDE + g + 8];
            #pragma unroll
            for (int ms = 0; ms < 2; ms++) {
                float h0 = tanh_fast(acc[ms][nt][0] + bias0);
                float h1 = tanh_fast(acc[ms][nt][1] + bias1);
                float h2 = tanh_fast(acc[ms][nt][2] + bias0);
                float h3 = tanh_fast(acc[ms][nt][3] + bias1);
                dot[ms][0] += h0 * t0a + h1 * t1a;
                nrm[ms][0] += h0 * h0 + h1 * h1;
                dot[ms][1] += h2 * t0b + h3 * t1b;
                nrm[ms][1] += h2 * h2 + h3 * h3;
            }
        }
        // reduce over the 4 lanes sharing (m, j)
        #pragma unroll
        for (int ms = 0; ms < 2; ms++)
            #pragma unroll
            for (int s1 = 0; s1 < 2; s1++) {
                float d = dot[ms][s1], q = nrm[ms][s1];
                d += __shfl_xor_sync(0xFFFFFFFF, d, 1);
                d += __shfl_xor_sync(0xFFFFFFFF, d, 2);
                q += __shfl_xor_sync(0xFFFFFFFF, q, 1);
                q += __shfl_xor_sync(0xFFFFFFFF, q, 2);
                if (l3 == 0) {
                    int m = wm * 2 + ms, j = g + s1 * 8;
                    s[F_REDD + wn * 128 + m * 16 + j] = d;
                    s[F_REDN + wn * 128 + m * 16 + j] = q;
                }
            }
    }
    __syncthreads();

    if (tid < 128) {                                 // cosine per (m, j)
        float d = s[F_REDD + tid] + s[F_REDD + 128 + tid];
        float q = s[F_REDN + tid] + s[F_REDN + 128 + tid];
        float hn = fmaxf(sqrtf(q), 1e-8f);
        s[F_COS + tid] = d / (hn * s[F_TNRM + (tid & 15)]);
    }
    __syncthreads();

    if (tid < 16) {                                  // softmax over 8 meta-paths
        float cv[MP], mx = -1e30f;
        #pragma unroll
        for (int m = 0; m < MP; m++) { cv[m] = s[F_COS + m * 16 + tid]; mx = fmaxf(mx, cv[m]); }
        float sum = 0.f;
        #pragma unroll
        for (int m = 0; m < MP; m++) { cv[m] = __expf(cv[m] - mx); sum += cv[m]; }
        float inv = 1.f / sum;
        #pragma unroll
        for (int m = 0; m < MP; m++) s[F_ATT + m * 16 + tid] = cv[m] * inv;
    }
    __syncthreads();

    // ---- final weighted sum from the resident raw-fp32 A tile ----
    {
        int j = tid >> 4, q = tid & 15;              // 16 threads per node
        float a[MP];
        #pragma unroll
        for (int m = 0; m < MP; m++) a[m] = s[F_ATT + m * 16 + j];
        const float4* A4 = (const float4*)(s + F_A); // row stride 65 float4
        float4* orow = (float4*)(outp + (size_t)(n0 + j) * DD);
        #pragma unroll
        for (int sQ = 0; sQ < 4; sQ++) {
            int k4 = q + sQ * 16;                    // 0..63
            float4 accv = make_float4(0.f, 0.f, 0.f, 0.f);
            #pragma unroll
            for (int m = 0; m < MP; m++) {
                float4 v = A4[(size_t)(m * 16 + j) * 65 + k4];
                accv.x += a[m] * v.x; accv.y += a[m] * v.y;
                accv.z += a[m] * v.z; accv.w += a[m] * v.w;
            }
            orow[k4] = accv;
        }
    }
}

// ---------------- launch ----------------
extern "C" void kernel_launch(void* const* d_in, const int* in_sizes, int n_in,
                              void* d_out, int out_size) {
    const int* nodes = nullptr;
    const float *homo = nullptr, *W = nullptr, *b = nullptr, *emb = nullptr;
    for (int i = 0; i < n_in; i++) {
        switch (in_sizes[i]) {
            case 100000:    nodes = (const int*)d_in[i];   break;  // nodes [N]
            case 204800000: homo  = (const float*)d_in[i]; break;  // homo  [M,N,D]
            case 65536:     W     = (const float*)d_in[i]; break;  // W     [H,D]
            case 256:       b     = (const float*)d_in[i]; break;  // b     [H]
            case 51200000:  emb   = (const float*)d_in[i]; break;  // out_embedding
        }
    }
    cudaFuncSetAttribute(hete_attn_kernel,
                         cudaFuncAttributeMaxDynamicSharedMemorySize, SMEM_REQ);
    hete_attn_kernel<<<NTOT / TN, THREADS, SMEM_REQ>>>(nodes, homo, W, b, emb, (float*)d_out);
}